// round 15
// baseline (speedup 1.0000x reference)
#include <cuda_runtime.h>
#include <cuda_fp16.h>
#include <cstdint>
#include <math.h>

#define NB 16
#define NC 160
#define HW 4096
#define IMW 64

// ---- scratch ----
__device__ float g_X[NB*3*HW];              // x = 2*s-1, [b][3][HW]
__device__ alignas(16) __half g_h0[NB*HW*NC];   // residual stream (NHWC, fp16)
__device__ alignas(16) __half g_h1[NB*HW*NC];
__device__ alignas(16) __half g_r0[NB*HW*NC];   // relu(h) stream
__device__ alignas(16) __half g_r1[NB*HW*NC];
__device__ float g_P[NB*HW*100];            // dmol params (NHWC)
__device__ alignas(16) __half g_wTb[5*5*320*160];  // [l][t][co 320][ci 160]
__device__ alignas(16) __half g_w1b[160*160];      // [co][ci]
__device__ alignas(16) __half g_w2b[100*160];

// ---------------- helpers ----------------
__device__ __forceinline__ uint32_t smem_u32(const void* p){
    uint32_t a;
    asm("{ .reg .u64 t; cvta.to.shared.u64 t, %1; cvt.u32.u64 %0, t; }" : "=r"(a) : "l"(p));
    return a;
}
// pack (lo, hi) floats into f16x2 (element0 = lo)
__device__ __forceinline__ uint32_t pk_f16(float lo, float hi){
    __half2 h = __floats2half2_rn(lo, hi);
    return *reinterpret_cast<uint32_t*>(&h);
}
// fp16-accumulate mma: D/C packed f16x2 pairs
__device__ __forceinline__ void mma16h(uint32_t* d, const uint32_t* a, uint32_t b0, uint32_t b1){
    asm volatile(
        "mma.sync.aligned.m16n8k16.row.col.f16.f16.f16.f16 "
        "{%0,%1},{%2,%3,%4,%5},{%6,%7},{%0,%1};"
        : "+r"(d[0]), "+r"(d[1])
        : "r"(a[0]), "r"(a[1]), "r"(a[2]), "r"(a[3]), "r"(b0), "r"(b1));
}
// f32-accumulate mma with f16 inputs (for 1x1 convs)
__device__ __forceinline__ void mma16f(float* d, const uint32_t* a, uint32_t b0, uint32_t b1){
    asm volatile(
        "mma.sync.aligned.m16n8k16.row.col.f32.f16.f16.f32 "
        "{%0,%1,%2,%3},{%4,%5,%6,%7},{%8,%9},{%0,%1,%2,%3};"
        : "+f"(d[0]), "+f"(d[1]), "+f"(d[2]), "+f"(d[3])
        : "r"(a[0]), "r"(a[1]), "r"(a[2]), "r"(a[3]), "r"(b0), "r"(b1));
}
__device__ __forceinline__ void ldsm4(uint32_t* r, uint32_t addr){
    asm volatile("ldmatrix.sync.aligned.m8n8.x4.shared.b16 {%0,%1,%2,%3}, [%4];"
        : "=r"(r[0]), "=r"(r[1]), "=r"(r[2]), "=r"(r[3]) : "r"(addr));
}
#define CP_CG(dst, src, sz) \
    asm volatile("cp.async.cg.shared.global [%0], [%1], 16, %2;" \
        :: "r"(dst), "l"(src), "r"(sz))
#define CP_COMMIT()  asm volatile("cp.async.commit_group;" ::: "memory")
#define CP_WAIT0()   asm volatile("cp.async.wait_group 0;" ::: "memory")

// ---------------- prep kernels ----------------
__global__ void zero_out_kernel(float* out){
    if (threadIdx.x < 16) out[threadIdx.x] = 0.f;
}
__global__ void prep_x_kernel(const float* __restrict__ s){
    int i = blockIdx.x*256 + threadIdx.x;
    if (i < NB*3*HW) g_X[i] = s[i]*2.f - 1.f;
}
// w_blk[l][co][ci][3][3] -> g_wTb[l][t][co][ci] (fp16)
__global__ void transpose_wblk_kernel(const float* __restrict__ w){
    int oidx = blockIdx.x*256 + threadIdx.x;
    if (oidx >= 5*5*320*160) return;
    int ci = oidx % 160; int r = oidx / 160;
    int co = r % 320;    r /= 320;
    int t  = r % 5;      int l = r / 5;
    g_wTb[oidx] = __float2half(w[((l*320 + co)*160 + ci)*9 + t]);
}
__global__ void prep_w12_kernel(const float* __restrict__ w1,
                                const float* __restrict__ w2){
    int i = blockIdx.x*256 + threadIdx.x;
    if (i < 160*160) g_w1b[i] = __float2half(w1[i]);
    if (i < 100*160) g_w2b[i] = __float2half(w2[i]);
}

// ---- masked 7x7 input conv (3 -> 160), fp16 h/hr NHWC output, 8-wide co tile ----
__global__ __launch_bounds__(256) void conv_in_kernel(const float* __restrict__ w_in){
    const int b   = blockIdx.z;
    const int co0 = blockIdx.y * 8;
    const int p   = blockIdx.x * 256 + threadIdx.x;
    __shared__ float sw[8][3][24];
    for (int idx = threadIdx.x; idx < 8*3*24; idx += 256){
        int cl  = idx / 72;
        int rem = idx % 72;
        int ci  = rem / 24;
        int t   = rem % 24;
        int ky  = (t < 21) ? (t / 7) : 3;
        int kx  = (t < 21) ? (t % 7) : (t - 21);
        sw[cl][ci][t] = w_in[((co0 + cl)*3 + ci)*49 + ky*7 + kx];
    }
    __syncthreads();
    const int y = p >> 6, x = p & 63;
    float acc[8] = {};
    #pragma unroll
    for (int ci = 0; ci < 3; ci++){
        const float* Xp = g_X + (b*3 + ci)*HW;
        #pragma unroll
        for (int t = 0; t < 24; t++){
            int ky = (t < 21) ? (t / 7) : 3;
            int kx = (t < 21) ? (t % 7) : (t - 21);
            int yy = y + ky - 3;
            int xx = x + kx - 3;
            float xv = (yy >= 0 && xx >= 0 && xx < IMW) ? Xp[yy*IMW + xx] : 0.f;
            #pragma unroll
            for (int cl = 0; cl < 8; cl++)
                acc[cl] = fmaf(sw[cl][ci][t], xv, acc[cl]);
        }
    }
    const size_t off = ((size_t)(b*HW) + p)*NC + co0;
    *reinterpret_cast<uint4*>(g_h0 + off) =
        make_uint4(pk_f16(acc[0], acc[1]), pk_f16(acc[2], acc[3]),
                   pk_f16(acc[4], acc[5]), pk_f16(acc[6], acc[7]));
    *reinterpret_cast<uint4*>(g_r0 + off) =
        make_uint4(pk_f16(fmaxf(acc[0],0.f), fmaxf(acc[1],0.f)),
                   pk_f16(fmaxf(acc[2],0.f), fmaxf(acc[3],0.f)),
                   pk_f16(fmaxf(acc[4],0.f), fmaxf(acc[5],0.f)),
                   pk_f16(fmaxf(acc[6],0.f), fmaxf(acc[7],0.f)));
}

// ---- gated residual block: fp16 mma (f16 acc) + ldmatrix + 2-stage cp.async ----
// smem (halves): A0 @0 [128][40], A1 @5120; W0 @10240 [160][40], W1 @16640
// total 23040 halves = 46080 B; 4 CTAs/SM target (64 regs)
#define GB_SMEM 46080
#define KC 32
__global__ __launch_bounds__(256, 4) void gated_block_mma(
        const __half* __restrict__ hin,
        const __half* __restrict__ hrin,
        __half* __restrict__ hout,
        __half* __restrict__ hrout,
        const __half* __restrict__ wl){
    extern __shared__ uint16_t smh[];
    const int b   = blockIdx.z;
    const int c0  = blockIdx.y * 80;   // pair-channel group base
    const int p0  = blockIdx.x * 128;  // pixel base
    const int tid = threadIdx.x;
    const int wid = tid >> 5, lane = tid & 31;
    const int wm  = wid & 3, wn = wid >> 2;
    const int gid = lane >> 2, tig = lane & 3;
    const uint32_t sbase = smem_u32(smh);

    // per-lane ldmatrix offsets (in halves)
    const int lj = lane >> 3, lr = lane & 7;
    const uint32_t laneA = (uint32_t)(((lj & 1)*8 + lr)*40 + (lj >> 1)*8);
    const uint32_t laneW = (uint32_t)(((lj >> 1)*80 + lr)*40 + (lj & 1)*8);
    const uint32_t aOffL = ((uint32_t)(wm*32)*40 + laneA)*2;
    const uint32_t wOffL = ((uint32_t)(wn*40)*40 + laneW)*2;

    const int tdy[5] = {-1,-1,-1, 0, 0};
    const int tdx[5] = {-1, 0, 1,-1, 0};

    uint32_t accA[2][5][2] = {};   // f16x2 packed accumulators
    uint32_t accB[2][5][2] = {};

    auto issueAW = [&](int it, int buf){
        const int t  = it / 5;
        const int kc = (it % 5) * KC;
        const int dy = tdy[t], dx = tdx[t];
        const uint32_t adst = sbase + (uint32_t)buf*10240;
        #pragma unroll
        for (int r = 0; r < 2; r++){
            int f  = tid + r*256;
            int px = f >> 2, q = f & 3;
            int p  = p0 + px;
            int y  = p >> 6, x = p & 63;
            int yy = y + dy, xx = x + dx;
            uint32_t sz = (yy >= 0 && xx >= 0 && xx < IMW) ? 16u : 0u;
            const __half* src =
                hrin + ((size_t)(b*HW) + yy*IMW + xx)*NC + kc + q*8;
            CP_CG(adst + (uint32_t)(px*80 + q*16), src, sz);
        }
        const __half* wg = wl + (size_t)t*320*160 + kc;
        const uint32_t wdst = sbase + 20480 + (uint32_t)buf*12800;
        #pragma unroll
        for (int r = 0; r < 3; r++){
            int f = tid + r*256;
            if (f < 640){
                int row = f >> 2, ch = f & 3;
                int co  = (row < 80) ? (c0 + row) : (160 + c0 + (row - 80));
                CP_CG(wdst + (uint32_t)(row*80 + ch*16),
                      wg + (size_t)co*160 + ch*8, 16u);
            }
        }
    };

    // prologue
    issueAW(0, 0);
    CP_COMMIT();

    for (int it = 0; it < 25; it++){
        const int buf = it & 1;
        CP_WAIT0();
        __syncthreads();
        if (it < 24){
            issueAW(it + 1, buf ^ 1);
            CP_COMMIT();
        }
        // MMA on current buffer (ldmatrix fragments)
        const uint32_t aB = sbase + (uint32_t)buf*10240 + aOffL;
        const uint32_t wB = sbase + 20480 + (uint32_t)buf*12800 + wOffL;
        #pragma unroll
        for (int ks = 0; ks < 2; ks++){
            const uint32_t ko = (uint32_t)ks*32;   // 16 halves = 32 B
            uint32_t a[2][4];
            ldsm4(a[0], aB + ko);
            ldsm4(a[1], aB + 16*40*2 + ko);
            #pragma unroll
            for (int n = 0; n < 5; n++){
                uint32_t w[4];
                ldsm4(w, wB + (uint32_t)(n*8*40)*2 + ko);
                mma16h(accA[0][n], a[0], w[0], w[1]);
                mma16h(accA[1][n], a[1], w[0], w[1]);
                mma16h(accB[0][n], a[0], w[2], w[3]);
                mma16h(accB[1][n], a[1], w[2], w[3]);
            }
        }
    }

    // epilogue: o = h_in + tanh(a)*sigmoid(b); write h and relu(h) (fp16)
    #pragma unroll
    for (int m = 0; m < 2; m++){
        const int r0 = p0 + wm*32 + m*16 + gid;
        #pragma unroll
        for (int n = 0; n < 5; n++){
            const int ch = c0 + wn*40 + n*8 + tig*2;
            #pragma unroll
            for (int h = 0; h < 2; h++){
                const int p = r0 + h*8;
                const size_t off = ((size_t)(b*HW) + p)*NC + ch;
                float2 hf = __half22float2(
                    *reinterpret_cast<const __half2*>(hin + off));
                float2 af = __half22float2(
                    *reinterpret_cast<__half2*>(&accA[m][n][h]));
                float2 gf = __half22float2(
                    *reinterpret_cast<__half2*>(&accB[m][n][h]));
                float ox = hf.x +
                    (1.f - 2.f/(1.f + __expf(2.f*af.x))) * (1.f/(1.f + __expf(-gf.x)));
                float oy = hf.y +
                    (1.f - 2.f/(1.f + __expf(2.f*af.y))) * (1.f/(1.f + __expf(-gf.y)));
                *reinterpret_cast<uint32_t*>(hout + off)  = pk_f16(ox, oy);
                *reinterpret_cast<uint32_t*>(hrout + off) =
                    pk_f16(fmaxf(ox, 0.f), fmaxf(oy, 0.f));
            }
        }
    }
}

// ---- 1x1 conv via f16-input f32-acc mma, cp.async staging, double buffered ----
// OUT_F32=0: out f16 relu (M=160); OUT_F32=1: out f32 (M=100)
template<int OUT_F32>
__global__ __launch_bounds__(256) void conv1x1_mma(const __half* __restrict__ in,
                                                   void* __restrict__ outv,
                                                   const __half* __restrict__ wb,
                                                   int M){
    __shared__ uint16_t sA[2][5120];   // [128][40]
    __shared__ uint16_t sW[2][3200];   // [80][40]
    const int b  = blockIdx.z;
    const int c0 = blockIdx.y * 80;
    const int p0 = blockIdx.x * 128;
    const int tid = threadIdx.x;
    const int wid = tid >> 5, lane = tid & 31;
    const int wm  = wid & 3, wn = wid >> 2;
    const int gid = lane >> 2, tig = lane & 3;
    const uint32_t sAa = smem_u32(sA);
    const uint32_t sWa = smem_u32(sW);

    float acc[2][5][4] = {};

    auto issue = [&](int ki, int buf){
        const int kc = ki*32;
        #pragma unroll
        for (int r = 0; r < 2; r++){
            int f  = tid + r*256;
            int px = f >> 2, q = f & 3;
            CP_CG(sAa + (uint32_t)buf*10240 + (uint32_t)(px*80 + q*16),
                  in + ((size_t)(b*HW) + p0 + px)*NC + kc + q*8, 16u);
        }
        // W tile: 80 rows x 4 chunks = 320 cp.asyncs -> two passes of 256 threads
        #pragma unroll
        for (int r = 0; r < 2; r++){
            int f = tid + r*256;
            if (f < 320){
                int row = f >> 2, ch = f & 3;
                int co  = c0 + row;
                uint32_t sz = (co < M) ? 16u : 0u;
                CP_CG(sWa + (uint32_t)buf*6400 + (uint32_t)(row*80 + ch*16),
                      wb + (size_t)co*160 + kc + ch*8, sz);
            }
        }
    };

    issue(0, 0);
    CP_COMMIT();

    for (int ki = 0; ki < 5; ki++){
        const int buf = ki & 1;
        CP_WAIT0();
        __syncthreads();
        if (ki < 4){
            issue(ki + 1, buf ^ 1);
            CP_COMMIT();
        }
        const uint16_t* pA = sA[buf] + (wm*32 + gid)*40 + tig*2;
        const uint16_t* pW = sW[buf] + (wn*40 + gid)*40 + tig*2;
        #pragma unroll
        for (int ks = 0; ks < 2; ks++){
            const int ko = ks*16;
            uint32_t a[2][4];
            #pragma unroll
            for (int m = 0; m < 2; m++){
                const uint16_t* ap = pA + m*16*40 + ko;
                a[m][0] = *reinterpret_cast<const uint32_t*>(ap);
                a[m][1] = *reinterpret_cast<const uint32_t*>(ap + 8*40);
                a[m][2] = *reinterpret_cast<const uint32_t*>(ap + 8);
                a[m][3] = *reinterpret_cast<const uint32_t*>(ap + 8*40 + 8);
            }
            #pragma unroll
            for (int n = 0; n < 5; n++){
                const uint16_t* q = pW + n*8*40 + ko;
                uint32_t b0 = *reinterpret_cast<const uint32_t*>(q);
                uint32_t b1 = *reinterpret_cast<const uint32_t*>(q + 8);
                #pragma unroll
                for (int m = 0; m < 2; m++)
                    mma16f(acc[m][n], a[m], b0, b1);
            }
        }
    }
    // epilogue
    #pragma unroll
    for (int m = 0; m < 2; m++){
        const int r0 = p0 + wm*32 + m*16 + gid;
        #pragma unroll
        for (int n = 0; n < 5; n++){
            const int co = c0 + wn*40 + n*8 + tig*2;
            if (co < M){
                #pragma unroll
                for (int h = 0; h < 2; h++){
                    const int p = r0 + h*8;
                    float ox = acc[m][n][h*2+0], oy = acc[m][n][h*2+1];
                    if (OUT_F32){
                        *reinterpret_cast<float2*>(
                            (float*)outv + ((size_t)(b*HW) + p)*M + co) =
                            make_float2(ox, oy);
                    } else {
                        *reinterpret_cast<uint32_t*>(
                            (__half*)outv + ((size_t)(b*HW) + p)*M + co) =
                            pk_f16(fmaxf(ox, 0.f), fmaxf(oy, 0.f));
                    }
                }
            }
        }
    }
}

// ---- DMOL log prob (NHWC params) ----
__device__ __forceinline__ float softplusf_(float x){
    return fmaxf(x, 0.f) + log1pf(expf(-fabsf(x)));
}
__device__ __forceinline__ float sigm_(float x){ return 1.f/(1.f + expf(-x)); }

__global__ __launch_bounds__(256) void dmol_kernel(float* __restrict__ out){
    const int b = blockIdx.y;
    const int p = blockIdx.x * 256 + threadIdx.x;
    const float* P = g_P + ((size_t)(b*HW) + p)*100;

    float xv[3];
    #pragma unroll
    for (int ch = 0; ch < 3; ch++) xv[ch] = g_X[(b*3 + ch)*HW + p];

    float lg[10];
    #pragma unroll
    for (int k = 0; k < 10; k++) lg[k] = P[k];
    float mx = lg[0];
    #pragma unroll
    for (int k = 1; k < 10; k++) mx = fmaxf(mx, lg[k]);
    float se = 0.f;
    #pragma unroll
    for (int k = 0; k < 10; k++) se += expf(lg[k] - mx);
    const float lse = mx + logf(se);

    float lp[10];
    #pragma unroll
    for (int k = 0; k < 10; k++){
        float m[3], ls[3], cf[3];
        #pragma unroll
        for (int ch = 0; ch < 3; ch++){
            m[ch]  = P[10 + 30*ch + k];
            ls[ch] = fmaxf(P[20 + 30*ch + k], -7.f);
            cf[ch] = tanhf(P[30 + 30*ch + k]);
        }
        m[1] += cf[0]*xv[0];
        m[2] += cf[1]*xv[0] + cf[2]*xv[1];
        float s = 0.f;
        #pragma unroll
        for (int ch = 0; ch < 3; ch++){
            float centered = xv[ch] - m[ch];
            float inv      = expf(-ls[ch]);
            float plus_in  = inv*(centered + 1.f/255.f);
            float min_in   = inv*(centered - 1.f/255.f);
            float cdfd     = sigm_(plus_in) - sigm_(min_in);
            float lcp      = plus_in - softplusf_(plus_in);
            float lomc     = -softplusf_(min_in);
            float mid      = inv*centered;
            float lpdf     = mid - ls[ch] - 2.f*softplusf_(mid);
            float lin      = (cdfd > 1e-5f) ? logf(fmaxf(cdfd, 1e-12f))
                                            : (lpdf - 4.8481164f);
            float lc = (xv[ch] < -0.999f) ? lcp
                     : ((xv[ch] > 0.999f) ? lomc : lin);
            s += lc;
        }
        lp[k] = s + (lg[k] - lse);
    }
    float m2 = lp[0];
    #pragma unroll
    for (int k = 1; k < 10; k++) m2 = fmaxf(m2, lp[k]);
    float s2 = 0.f;
    #pragma unroll
    for (int k = 0; k < 10; k++) s2 += expf(lp[k] - m2);
    float pix_lp = m2 + logf(s2);

    __shared__ float red[256];
    red[threadIdx.x] = pix_lp;
    __syncthreads();
    #pragma unroll
    for (int s = 128; s > 0; s >>= 1){
        if (threadIdx.x < s) red[threadIdx.x] += red[threadIdx.x + s];
        __syncthreads();
    }
    if (threadIdx.x == 0) atomicAdd(&out[b], red[0]);
}

extern "C" void kernel_launch(void* const* d_in, const int* in_sizes, int n_in,
                              void* d_out, int out_size){
    const float* samples = (const float*)d_in[0];
    const float* w_in    = (const float*)d_in[1];
    const float* w_blk   = (const float*)d_in[2];
    const float* w_out1  = (const float*)d_in[3];
    const float* w_out2  = (const float*)d_in[4];
    float* out = (float*)d_out;

    cudaFuncSetAttribute(gated_block_mma,
                         cudaFuncAttributeMaxDynamicSharedMemorySize, GB_SMEM);

    __half *d_h0, *d_h1, *d_r0, *d_r1, *d_wT, *d_w1, *d_w2;
    float* d_P;
    cudaGetSymbolAddress((void**)&d_h0, g_h0);
    cudaGetSymbolAddress((void**)&d_h1, g_h1);
    cudaGetSymbolAddress((void**)&d_r0, g_r0);
    cudaGetSymbolAddress((void**)&d_r1, g_r1);
    cudaGetSymbolAddress((void**)&d_P,  g_P);
    cudaGetSymbolAddress((void**)&d_wT, g_wTb);
    cudaGetSymbolAddress((void**)&d_w1, g_w1b);
    cudaGetSymbolAddress((void**)&d_w2, g_w2b);

    // launch order keeps gated_block_mma(l=0) at launch index 3 (ncu window).
    prep_x_kernel<<<(NB*3*HW + 255)/256, 256>>>(samples);                 // 0
    transpose_wblk_kernel<<<(5*5*320*160 + 255)/256, 256>>>(w_blk);       // 1
    conv_in_kernel<<<dim3(16, 20, NB), 256>>>(w_in);                      // 2 -> h0/r0

    for (int l = 0; l < 5; l++){                                          // 3..7
        const __half* hin  = (l & 1) ? d_h1 : d_h0;
        const __half* hrin = (l & 1) ? d_r1 : d_r0;
        __half* hout  = (l & 1) ? d_h0 : d_h1;
        __half* hrout = (l & 1) ? d_r0 : d_r1;
        gated_block_mma<<<dim3(32, 2, NB), 256, GB_SMEM>>>(
            hin, hrin, hout, hrout, d_wT + (size_t)l*5*320*160);
    }
    // after layer 4 (l even: h0->h1), final h in h1, relu(h) in r1

    zero_out_kernel<<<1, 32>>>(out);                                      // 8
    prep_w12_kernel<<<100, 256>>>(w_out1, w_out2);                        // 9

    // h2 = relu(W1 @ r1) -> r0 (f16)
    conv1x1_mma<0><<<dim3(32, 2, NB), 256>>>(d_r1, (void*)d_r0, d_w1, 160); // 10
    // params = W2 @ h2 -> P (f32)
    conv1x1_mma<1><<<dim3(32, 2, NB), 256>>>(d_r0, (void*)d_P, d_w2, 100);  // 11

    dmol_kernel<<<dim3(16, NB), 256>>>(out);                              // 12
}

// round 16
// speedup vs baseline: 1.0738x; 1.0738x over previous
#include <cuda_runtime.h>
#include <cuda_fp16.h>
#include <cstdint>
#include <math.h>

#define NB 16
#define NC 160
#define HW 4096
#define IMW 64

// ---- scratch ----
__device__ float g_X[NB*3*HW];              // x = 2*s-1, [b][3][HW]
__device__ alignas(16) __half g_h0[NB*HW*NC];   // residual stream (NHWC, fp16)
__device__ alignas(16) __half g_h1[NB*HW*NC];
__device__ alignas(16) __half g_r0[NB*HW*NC];   // relu(h) stream
__device__ alignas(16) __half g_r1[NB*HW*NC];
__device__ float g_P[NB*HW*100];            // dmol params (NHWC)
__device__ alignas(16) __half g_wTb[5*5*320*160];  // [l][t][co 320][ci 160]
__device__ alignas(16) __half g_w1b[160*160];      // [co][ci]
__device__ alignas(16) __half g_w2b[100*160];

// ---------------- helpers ----------------
__device__ __forceinline__ uint32_t smem_u32(const void* p){
    uint32_t a;
    asm("{ .reg .u64 t; cvta.to.shared.u64 t, %1; cvt.u32.u64 %0, t; }" : "=r"(a) : "l"(p));
    return a;
}
// pack (lo, hi) floats into f16x2 (element0 = lo)
__device__ __forceinline__ uint32_t pk_f16(float lo, float hi){
    __half2 h = __floats2half2_rn(lo, hi);
    return *reinterpret_cast<uint32_t*>(&h);
}
// fp16-accumulate mma: D/C packed f16x2 pairs
__device__ __forceinline__ void mma16h(uint32_t* d, const uint32_t* a, uint32_t b0, uint32_t b1){
    asm volatile(
        "mma.sync.aligned.m16n8k16.row.col.f16.f16.f16.f16 "
        "{%0,%1},{%2,%3,%4,%5},{%6,%7},{%0,%1};"
        : "+r"(d[0]), "+r"(d[1])
        : "r"(a[0]), "r"(a[1]), "r"(a[2]), "r"(a[3]), "r"(b0), "r"(b1));
}
// f32-accumulate mma with f16 inputs (for 1x1 convs)
__device__ __forceinline__ void mma16f(float* d, const uint32_t* a, uint32_t b0, uint32_t b1){
    asm volatile(
        "mma.sync.aligned.m16n8k16.row.col.f32.f16.f16.f32 "
        "{%0,%1,%2,%3},{%4,%5,%6,%7},{%8,%9},{%0,%1,%2,%3};"
        : "+f"(d[0]), "+f"(d[1]), "+f"(d[2]), "+f"(d[3])
        : "r"(a[0]), "r"(a[1]), "r"(a[2]), "r"(a[3]), "r"(b0), "r"(b1));
}
__device__ __forceinline__ void ldsm4(uint32_t* r, uint32_t addr){
    asm volatile("ldmatrix.sync.aligned.m8n8.x4.shared.b16 {%0,%1,%2,%3}, [%4];"
        : "=r"(r[0]), "=r"(r[1]), "=r"(r[2]), "=r"(r[3]) : "r"(addr));
}
#define CP_CG(dst, src, sz) \
    asm volatile("cp.async.cg.shared.global [%0], [%1], 16, %2;" \
        :: "r"(dst), "l"(src), "r"(sz))
#define CP_COMMIT()  asm volatile("cp.async.commit_group;" ::: "memory")
#define CP_WAIT0()   asm volatile("cp.async.wait_group 0;" ::: "memory")

// ---------------- prep kernels ----------------
__global__ void zero_out_kernel(float* out){
    if (threadIdx.x < 16) out[threadIdx.x] = 0.f;
}
__global__ void prep_x_kernel(const float* __restrict__ s){
    int i = blockIdx.x*256 + threadIdx.x;
    if (i < NB*3*HW) g_X[i] = s[i]*2.f - 1.f;
}
// w_blk[l][co][ci][3][3] -> g_wTb[l][t][co][ci] (fp16)
__global__ void transpose_wblk_kernel(const float* __restrict__ w){
    int oidx = blockIdx.x*256 + threadIdx.x;
    if (oidx >= 5*5*320*160) return;
    int ci = oidx % 160; int r = oidx / 160;
    int co = r % 320;    r /= 320;
    int t  = r % 5;      int l = r / 5;
    g_wTb[oidx] = __float2half(w[((l*320 + co)*160 + ci)*9 + t]);
}
__global__ void prep_w12_kernel(const float* __restrict__ w1,
                                const float* __restrict__ w2){
    int i = blockIdx.x*256 + threadIdx.x;
    if (i < 160*160) g_w1b[i] = __float2half(w1[i]);
    if (i < 100*160) g_w2b[i] = __float2half(w2[i]);
}

// ---- masked 7x7 input conv (3 -> 160), fp16 h/hr NHWC output, 8-wide co tile ----
__global__ __launch_bounds__(256) void conv_in_kernel(const float* __restrict__ w_in){
    const int b   = blockIdx.z;
    const int co0 = blockIdx.y * 8;
    const int p   = blockIdx.x * 256 + threadIdx.x;
    __shared__ float sw[8][3][24];
    for (int idx = threadIdx.x; idx < 8*3*24; idx += 256){
        int cl  = idx / 72;
        int rem = idx % 72;
        int ci  = rem / 24;
        int t   = rem % 24;
        int ky  = (t < 21) ? (t / 7) : 3;
        int kx  = (t < 21) ? (t % 7) : (t - 21);
        sw[cl][ci][t] = w_in[((co0 + cl)*3 + ci)*49 + ky*7 + kx];
    }
    __syncthreads();
    const int y = p >> 6, x = p & 63;
    float acc[8] = {};
    #pragma unroll
    for (int ci = 0; ci < 3; ci++){
        const float* Xp = g_X + (b*3 + ci)*HW;
        #pragma unroll
        for (int t = 0; t < 24; t++){
            int ky = (t < 21) ? (t / 7) : 3;
            int kx = (t < 21) ? (t % 7) : (t - 21);
            int yy = y + ky - 3;
            int xx = x + kx - 3;
            float xv = (yy >= 0 && xx >= 0 && xx < IMW) ? Xp[yy*IMW + xx] : 0.f;
            #pragma unroll
            for (int cl = 0; cl < 8; cl++)
                acc[cl] = fmaf(sw[cl][ci][t], xv, acc[cl]);
        }
    }
    const size_t off = ((size_t)(b*HW) + p)*NC + co0;
    *reinterpret_cast<uint4*>(g_h0 + off) =
        make_uint4(pk_f16(acc[0], acc[1]), pk_f16(acc[2], acc[3]),
                   pk_f16(acc[4], acc[5]), pk_f16(acc[6], acc[7]));
    *reinterpret_cast<uint4*>(g_r0 + off) =
        make_uint4(pk_f16(fmaxf(acc[0],0.f), fmaxf(acc[1],0.f)),
                   pk_f16(fmaxf(acc[2],0.f), fmaxf(acc[3],0.f)),
                   pk_f16(fmaxf(acc[4],0.f), fmaxf(acc[5],0.f)),
                   pk_f16(fmaxf(acc[6],0.f), fmaxf(acc[7],0.f)));
}

// ---- gated residual block: fp16 mma (f16 acc) + ldmatrix + 2-stage cp.async ----
// smem (halves): A0 @0 [128][40], A1 @5120; W0 @10240 [160][40], W1 @16640
// total 23040 halves = 46080 B; 3 CTAs/SM
#define GB_SMEM 46080
#define KC 32
__global__ __launch_bounds__(256, 3) void gated_block_mma(
        const __half* __restrict__ hin,
        const __half* __restrict__ hrin,
        __half* __restrict__ hout,
        __half* __restrict__ hrout,
        const __half* __restrict__ wl){
    extern __shared__ uint16_t smh[];
    const int b   = blockIdx.z;
    const int c0  = blockIdx.y * 80;   // pair-channel group base
    const int p0  = blockIdx.x * 128;  // pixel base
    const int tid = threadIdx.x;
    const int wid = tid >> 5, lane = tid & 31;
    const int wm  = wid & 3, wn = wid >> 2;
    const int gid = lane >> 2, tig = lane & 3;
    const uint32_t sbase = smem_u32(smh);

    // per-lane ldmatrix offsets (in halves)
    const int lj = lane >> 3, lr = lane & 7;
    const uint32_t laneA = (uint32_t)(((lj & 1)*8 + lr)*40 + (lj >> 1)*8);
    const uint32_t laneW = (uint32_t)(((lj >> 1)*80 + lr)*40 + (lj & 1)*8);
    const uint32_t aOffL = ((uint32_t)(wm*32)*40 + laneA)*2;
    const uint32_t wOffL = ((uint32_t)(wn*40)*40 + laneW)*2;

    // ---- hoisted staging geometry (loop-invariant per thread) ----
    // A: r-pass 0 handles pixel px0 = tid>>2, r-pass 1 handles px0+64 (= +1 image row)
    const int qa   = tid & 3;
    const int pxp  = p0 + (tid >> 2);
    const int y0   = pxp >> 6, x0 = pxp & 63;
    const uint32_t aSrc0 = ((uint32_t)(b*HW) + (uint32_t)(y0*IMW + x0))*NC + qa*8;
    const uint32_t aDst0 = sbase + (uint32_t)((tid >> 2)*80 + qa*16);
    // W: pass r handles row = (tid + r*256)>>2, ch = tid&3; co select hoisted
    uint32_t wSrc[3];
    {
        #pragma unroll
        for (int r = 0; r < 3; r++){
            int f = tid + r*256;
            int row = f >> 2;
            int co  = (row < 80) ? (c0 + row) : (160 + c0 + (row - 80));
            wSrc[r] = (uint32_t)co*160 + qa*8;
        }
    }
    const uint32_t wDst0 = sbase + 20480 + (uint32_t)((tid >> 2)*80 + qa*16);

    uint32_t accA[2][5][2] = {};   // f16x2 packed accumulators
    uint32_t accB[2][5][2] = {};

    // issue staging for (tap t, k-chunk kc) into buffer buf
    auto issueAW = [&](int t, int kc, int buf){
        const int dy = (t < 3) ? -1 : 0;
        const int dx = (t < 3) ? (t - 1) : (t - 4);
        const int yy = y0 + dy, xx = x0 + dx;
        const uint32_t adst = aDst0 + (uint32_t)buf*10240;
        const __half* s0 = hrin + aSrc0 + (dy*IMW + dx)*NC + kc;
        uint32_t sz0 = ((unsigned)yy < (unsigned)IMW && (unsigned)xx < (unsigned)IMW) ? 16u : 0u;
        uint32_t sz1 = ((unsigned)(yy+1) < (unsigned)IMW && (unsigned)xx < (unsigned)IMW) ? 16u : 0u;
        CP_CG(adst,        s0,          sz0);
        CP_CG(adst + 5120, s0 + 64*NC,  sz1);
        const __half* wg = wl + (size_t)t*(320*160) + kc;
        const uint32_t wdst = wDst0 + (uint32_t)buf*12800;
        CP_CG(wdst,          wg + wSrc[0], 16u);
        CP_CG(wdst +  5120,  wg + wSrc[1], 16u);
        if (tid < 128)
            CP_CG(wdst + 10240, wg + wSrc[2], 16u);
    };

    // prologue
    issueAW(0, 0, 0);
    CP_COMMIT();

    int tn = 0, k5n = 1;   // tap / k-chunk of next issue (index it+1)
    for (int it = 0; it < 25; it++){
        const int buf = it & 1;
        CP_WAIT0();
        __syncthreads();
        if (it < 24){
            issueAW(tn, k5n*KC, buf ^ 1);
            CP_COMMIT();
        }
        // MMA on current buffer (ldmatrix fragments)
        const uint32_t aB = sbase + (uint32_t)buf*10240 + aOffL;
        const uint32_t wB = sbase + 20480 + (uint32_t)buf*12800 + wOffL;
        #pragma unroll
        for (int ks = 0; ks < 2; ks++){
            const uint32_t ko = (uint32_t)ks*32;   // 16 halves = 32 B
            uint32_t a[2][4];
            ldsm4(a[0], aB + ko);
            ldsm4(a[1], aB + 16*40*2 + ko);
            #pragma unroll
            for (int n = 0; n < 5; n++){
                uint32_t w[4];
                ldsm4(w, wB + (uint32_t)(n*8*40)*2 + ko);
                mma16h(accA[0][n], a[0], w[0], w[1]);
                mma16h(accA[1][n], a[1], w[0], w[1]);
                mma16h(accB[0][n], a[0], w[2], w[3]);
                mma16h(accB[1][n], a[1], w[2], w[3]);
            }
        }
        k5n++; if (k5n == 5){ k5n = 0; tn++; }
    }

    // epilogue: o = h_in + tanh(a)*sigmoid(b); write h and relu(h) (fp16)
    #pragma unroll
    for (int m = 0; m < 2; m++){
        const int r0 = p0 + wm*32 + m*16 + gid;
        #pragma unroll
        for (int n = 0; n < 5; n++){
            const int ch = c0 + wn*40 + n*8 + tig*2;
            #pragma unroll
            for (int h = 0; h < 2; h++){
                const int p = r0 + h*8;
                const size_t off = ((size_t)(b*HW) + p)*NC + ch;
                float2 hf = __half22float2(
                    *reinterpret_cast<const __half2*>(hin + off));
                float2 af = __half22float2(
                    *reinterpret_cast<__half2*>(&accA[m][n][h]));
                float2 gf = __half22float2(
                    *reinterpret_cast<__half2*>(&accB[m][n][h]));
                float ox = hf.x +
                    (1.f - 2.f/(1.f + __expf(2.f*af.x))) * (1.f/(1.f + __expf(-gf.x)));
                float oy = hf.y +
                    (1.f - 2.f/(1.f + __expf(2.f*af.y))) * (1.f/(1.f + __expf(-gf.y)));
                *reinterpret_cast<uint32_t*>(hout + off)  = pk_f16(ox, oy);
                *reinterpret_cast<uint32_t*>(hrout + off) =
                    pk_f16(fmaxf(ox, 0.f), fmaxf(oy, 0.f));
            }
        }
    }
}

// ---- 1x1 conv via f16-input f32-acc mma, cp.async staging, double buffered ----
// OUT_F32=0: out f16 relu (M=160); OUT_F32=1: out f32 (M=100)
template<int OUT_F32>
__global__ __launch_bounds__(256) void conv1x1_mma(const __half* __restrict__ in,
                                                   void* __restrict__ outv,
                                                   const __half* __restrict__ wb,
                                                   int M){
    __shared__ uint16_t sA[2][5120];   // [128][40]
    __shared__ uint16_t sW[2][3200];   // [80][40]
    const int b  = blockIdx.z;
    const int c0 = blockIdx.y * 80;
    const int p0 = blockIdx.x * 128;
    const int tid = threadIdx.x;
    const int wid = tid >> 5, lane = tid & 31;
    const int wm  = wid & 3, wn = wid >> 2;
    const int gid = lane >> 2, tig = lane & 3;
    const uint32_t sAa = smem_u32(sA);
    const uint32_t sWa = smem_u32(sW);

    float acc[2][5][4] = {};

    auto issue = [&](int ki, int buf){
        const int kc = ki*32;
        #pragma unroll
        for (int r = 0; r < 2; r++){
            int f  = tid + r*256;
            int px = f >> 2, q = f & 3;
            CP_CG(sAa + (uint32_t)buf*10240 + (uint32_t)(px*80 + q*16),
                  in + ((size_t)(b*HW) + p0 + px)*NC + kc + q*8, 16u);
        }
        // W tile: 80 rows x 4 chunks = 320 cp.asyncs -> two passes of 256 threads
        #pragma unroll
        for (int r = 0; r < 2; r++){
            int f = tid + r*256;
            if (f < 320){
                int row = f >> 2, ch = f & 3;
                int co  = c0 + row;
                uint32_t sz = (co < M) ? 16u : 0u;
                CP_CG(sWa + (uint32_t)buf*6400 + (uint32_t)(row*80 + ch*16),
                      wb + (size_t)co*160 + kc + ch*8, sz);
            }
        }
    };

    issue(0, 0);
    CP_COMMIT();

    for (int ki = 0; ki < 5; ki++){
        const int buf = ki & 1;
        CP_WAIT0();
        __syncthreads();
        if (ki < 4){
            issue(ki + 1, buf ^ 1);
            CP_COMMIT();
        }
        const uint16_t* pA = sA[buf] + (wm*32 + gid)*40 + tig*2;
        const uint16_t* pW = sW[buf] + (wn*40 + gid)*40 + tig*2;
        #pragma unroll
        for (int ks = 0; ks < 2; ks++){
            const int ko = ks*16;
            uint32_t a[2][4];
            #pragma unroll
            for (int m = 0; m < 2; m++){
                const uint16_t* ap = pA + m*16*40 + ko;
                a[m][0] = *reinterpret_cast<const uint32_t*>(ap);
                a[m][1] = *reinterpret_cast<const uint32_t*>(ap + 8*40);
                a[m][2] = *reinterpret_cast<const uint32_t*>(ap + 8);
                a[m][3] = *reinterpret_cast<const uint32_t*>(ap + 8*40 + 8);
            }
            #pragma unroll
            for (int n = 0; n < 5; n++){
                const uint16_t* q = pW + n*8*40 + ko;
                uint32_t b0 = *reinterpret_cast<const uint32_t*>(q);
                uint32_t b1 = *reinterpret_cast<const uint32_t*>(q + 8);
                #pragma unroll
                for (int m = 0; m < 2; m++)
                    mma16f(acc[m][n], a[m], b0, b1);
            }
        }
    }
    // epilogue
    #pragma unroll
    for (int m = 0; m < 2; m++){
        const int r0 = p0 + wm*32 + m*16 + gid;
        #pragma unroll
        for (int n = 0; n < 5; n++){
            const int co = c0 + wn*40 + n*8 + tig*2;
            if (co < M){
                #pragma unroll
                for (int h = 0; h < 2; h++){
                    const int p = r0 + h*8;
                    float ox = acc[m][n][h*2+0], oy = acc[m][n][h*2+1];
                    if (OUT_F32){
                        *reinterpret_cast<float2*>(
                            (float*)outv + ((size_t)(b*HW) + p)*M + co) =
                            make_float2(ox, oy);
                    } else {
                        *reinterpret_cast<uint32_t*>(
                            (__half*)outv + ((size_t)(b*HW) + p)*M + co) =
                            pk_f16(fmaxf(ox, 0.f), fmaxf(oy, 0.f));
                    }
                }
            }
        }
    }
}

// ---- DMOL log prob (NHWC params) ----
__device__ __forceinline__ float softplusf_(float x){
    return fmaxf(x, 0.f) + log1pf(expf(-fabsf(x)));
}
__device__ __forceinline__ float sigm_(float x){ return 1.f/(1.f + expf(-x)); }

__global__ __launch_bounds__(256) void dmol_kernel(float* __restrict__ out){
    const int b = blockIdx.y;
    const int p = blockIdx.x * 256 + threadIdx.x;
    const float* P = g_P + ((size_t)(b*HW) + p)*100;

    float xv[3];
    #pragma unroll
    for (int ch = 0; ch < 3; ch++) xv[ch] = g_X[(b*3 + ch)*HW + p];

    float lg[10];
    #pragma unroll
    for (int k = 0; k < 10; k++) lg[k] = P[k];
    float mx = lg[0];
    #pragma unroll
    for (int k = 1; k < 10; k++) mx = fmaxf(mx, lg[k]);
    float se = 0.f;
    #pragma unroll
    for (int k = 0; k < 10; k++) se += expf(lg[k] - mx);
    const float lse = mx + logf(se);

    float lp[10];
    #pragma unroll
    for (int k = 0; k < 10; k++){
        float m[3], ls[3], cf[3];
        #pragma unroll
        for (int ch = 0; ch < 3; ch++){
            m[ch]  = P[10 + 30*ch + k];
            ls[ch] = fmaxf(P[20 + 30*ch + k], -7.f);
            cf[ch] = tanhf(P[30 + 30*ch + k]);
        }
        m[1] += cf[0]*xv[0];
        m[2] += cf[1]*xv[0] + cf[2]*xv[1];
        float s = 0.f;
        #pragma unroll
        for (int ch = 0; ch < 3; ch++){
            float centered = xv[ch] - m[ch];
            float inv      = expf(-ls[ch]);
            float plus_in  = inv*(centered + 1.f/255.f);
            float min_in   = inv*(centered - 1.f/255.f);
            float cdfd     = sigm_(plus_in) - sigm_(min_in);
            float lcp      = plus_in - softplusf_(plus_in);
            float lomc     = -softplusf_(min_in);
            float mid      = inv*centered;
            float lpdf     = mid - ls[ch] - 2.f*softplusf_(mid);
            float lin      = (cdfd > 1e-5f) ? logf(fmaxf(cdfd, 1e-12f))
                                            : (lpdf - 4.8481164f);
            float lc = (xv[ch] < -0.999f) ? lcp
                     : ((xv[ch] > 0.999f) ? lomc : lin);
            s += lc;
        }
        lp[k] = s + (lg[k] - lse);
    }
    float m2 = lp[0];
    #pragma unroll
    for (int k = 1; k < 10; k++) m2 = fmaxf(m2, lp[k]);
    float s2 = 0.f;
    #pragma unroll
    for (int k = 0; k < 10; k++) s2 += expf(lp[k] - m2);
    float pix_lp = m2 + logf(s2);

    __shared__ float red[256];
    red[threadIdx.x] = pix_lp;
    __syncthreads();
    #pragma unroll
    for (int s = 128; s > 0; s >>= 1){
        if (threadIdx.x < s) red[threadIdx.x] += red[threadIdx.x + s];
        __syncthreads();
    }
    if (threadIdx.x == 0) atomicAdd(&out[b], red[0]);
}

extern "C" void kernel_launch(void* const* d_in, const int* in_sizes, int n_in,
                              void* d_out, int out_size){
    const float* samples = (const float*)d_in[0];
    const float* w_in    = (const float*)d_in[1];
    const float* w_blk   = (const float*)d_in[2];
    const float* w_out1  = (const float*)d_in[3];
    const float* w_out2  = (const float*)d_in[4];
    float* out = (float*)d_out;

    cudaFuncSetAttribute(gated_block_mma,
                         cudaFuncAttributeMaxDynamicSharedMemorySize, GB_SMEM);

    __half *d_h0, *d_h1, *d_r0, *d_r1, *d_wT, *d_w1, *d_w2;
    float* d_P;
    cudaGetSymbolAddress((void**)&d_h0, g_h0);
    cudaGetSymbolAddress((void**)&d_h1, g_h1);
    cudaGetSymbolAddress((void**)&d_r0, g_r0);
    cudaGetSymbolAddress((void**)&d_r1, g_r1);
    cudaGetSymbolAddress((void**)&d_P,  g_P);
    cudaGetSymbolAddress((void**)&d_wT, g_wTb);
    cudaGetSymbolAddress((void**)&d_w1, g_w1b);
    cudaGetSymbolAddress((void**)&d_w2, g_w2b);

    // launch order keeps gated_block_mma(l=0) at launch index 3 (ncu window).
    prep_x_kernel<<<(NB*3*HW + 255)/256, 256>>>(samples);                 // 0
    transpose_wblk_kernel<<<(5*5*320*160 + 255)/256, 256>>>(w_blk);       // 1
    conv_in_kernel<<<dim3(16, 20, NB), 256>>>(w_in);                      // 2 -> h0/r0

    for (int l = 0; l < 5; l++){                                          // 3..7
        const __half* hin  = (l & 1) ? d_h1 : d_h0;
        const __half* hrin = (l & 1) ? d_r1 : d_r0;
        __half* hout  = (l & 1) ? d_h0 : d_h1;
        __half* hrout = (l & 1) ? d_r0 : d_r1;
        gated_block_mma<<<dim3(32, 2, NB), 256, GB_SMEM>>>(
            hin, hrin, hout, hrout, d_wT + (size_t)l*5*320*160);
    }
    // after layer 4 (l even: h0->h1), final h in h1, relu(h) in r1

    zero_out_kernel<<<1, 32>>>(out);                                      // 8
    prep_w12_kernel<<<100, 256>>>(w_out1, w_out2);                        // 9

    // h2 = relu(W1 @ r1) -> r0 (f16)
    conv1x1_mma<0><<<dim3(32, 2, NB), 256>>>(d_r1, (void*)d_r0, d_w1, 160); // 10
    // params = W2 @ h2 -> P (f32)
    conv1x1_mma<1><<<dim3(32, 2, NB), 256>>>(d_r0, (void*)d_P, d_w2, 100);  // 11

    dmol_kernel<<<dim3(16, NB), 256>>>(out);                              // 12
}